// round 15
// baseline (speedup 1.0000x reference)
#include <cuda_runtime.h>
#include <math.h>

#define NB 8
#define NG 512
#define NT 1024
#define NK 5
#define NC 3

#define PREP_TPB 256
#define MAIN_TPB 128
#define TGRP (NT / MAIN_TPB)     // 8 target-groups
#define NCHUNK 16
#define CHUNK_G (NG / NCHUNK)    // 32 grid rows per chunk

// device scratch (allocation-free per harness rules)
__device__ float4 d_q1[NB * NG];   // {2x0', 2x1', 2x2', h0*2^(-x0'^2)}
__device__ float2 d_q2[NB * NG];   // {h1*2^(-x1'^2), h2*2^(-x2'^2)}
__device__ float4 d_runi;          // {r0, r1, r2, uni?1:0}

__device__ __forceinline__ float ex2f(float x) {
    float y;
    asm("ex2.approx.ftz.f32 %0, %1;" : "=f"(y) : "f"(x));
    return y;
}

// ---------------- prep: 16 fold blocks + 24 out-init blocks ----------------
__global__ __launch_bounds__(PREP_TPB)
void prep_kernel(const float* __restrict__ x_grid,
                 const float* __restrict__ h_grid,
                 const float* __restrict__ sigma,
                 const float* __restrict__ g_w,
                 const float* __restrict__ g_b,
                 float4* __restrict__ out4)
{
    __shared__ __align__(16) float sh[256 * NK * NC];   // 3840 floats = 15KB

    const int tid = threadIdx.x;
    const int blk = blockIdx.x;

    if (blk < 16) {
        // coefficients (tiny, every thread)
        float a2[NK][NC];
        #pragma unroll
        for (int k = 0; k < NK; k++)
            #pragma unroll
            for (int c = 0; c < NC; c++) {
                float s   = __expf(sigma[k * NC + c]) + 1e-6f;
                float inv = 1.0f / s;
                a2[k][c]  = -0.5f * 1.4426950408889634f * inv * inv;
            }
        bool uni = true;
        #pragma unroll
        for (int k = 1; k < NK; k++)
            #pragma unroll
            for (int c = 0; c < NC; c++)
                uni = uni && (a2[k][c] == a2[0][c]);

        const float r0 = uni ? sqrtf(-a2[0][0]) : 1.0f;
        const float r1 = uni ? sqrtf(-a2[0][1]) : 1.0f;
        const float r2 = uni ? sqrtf(-a2[0][2]) : 1.0f;

        if (blk == 0 && tid == 0)
            d_runi = make_float4(r0, r1, r2, uni ? 1.0f : 0.0f);

        // ---- fold rows rbase .. rbase+255 (coalesced bounce) ----
        const int rbase = blk * 256;
        const float4* hg4 = (const float4*)(h_grid) + rbase * (NK * NC) / 4;
        #pragma unroll
        for (int i = 0; i < 4; i++) {
            int idx = tid + i * PREP_TPB;
            if (idx < 960) ((float4*)sh)[idx] = hg4[idx];
        }
        __syncthreads();

        const int row = rbase + tid;
        const float* hp = sh + tid * (NK * NC);   // stride 15: conflict-free
        float gw[NK];
        #pragma unroll
        for (int k = 0; k < NK; k++) gw[k] = g_w[k];
        float h0 = 0.f, h1 = 0.f, h2 = 0.f;
        #pragma unroll
        for (int k = 0; k < NK; k++) {
            h0 += gw[k] * hp[k * NC + 0];
            h1 += gw[k] * hp[k * NC + 1];
            h2 += gw[k] * hp[k * NC + 2];
        }
        const float* xp = x_grid + row * NC;
        const float sx0 = xp[0] * r0, sx1 = xp[1] * r1, sx2 = xp[2] * r2;
        // fold per-g exponent constant into h
        h0 *= ex2f(-sx0 * sx0);
        h1 *= ex2f(-sx1 * sx1);
        h2 *= ex2f(-sx2 * sx2);
        d_q1[row] = make_float4(2.f * sx0, 2.f * sx1, 2.f * sx2, h0);
        d_q2[row] = make_float2(h1, h2);
    } else {
        // ---- out := bias (24 blocks x 256 = 6144 float4) ----
        const int i = (blk - 16) * PREP_TPB + tid;
        const float bb = g_b[0];
        out4[i] = make_float4(bb, bb, bb, bb);
    }

    // allow dependent (main) grid to launch/run its pre-wait prologue early
    asm volatile("griddepcontrol.launch_dependents;");
}

// ---------------- main: thread-per-target, 32-row g-chunk, PDL ----------------
__global__ __launch_bounds__(MAIN_TPB)
void main_kernel(const float* __restrict__ x_grid,
                 const float* __restrict__ h_grid,
                 const float* __restrict__ target_x,
                 const float* __restrict__ sigma,
                 const float* __restrict__ g_w,
                 float* __restrict__ out)
{
    __shared__ __align__(16) float4 s1[CHUNK_G];
    __shared__ __align__(16) float2 s2[CHUNK_G];

    const int tid    = threadIdx.x;
    const int tgroup = blockIdx.x;
    const int chunk  = blockIdx.y;
    const int b      = blockIdx.z;
    const int g0     = chunk * CHUNK_G;
    const int gbase  = b * NG + g0;

    // ---- pre-wait prologue: raw targets (independent of prep) ----
    const int t     = tgroup * MAIN_TPB + tid;
    const int obase = (b * NT + t) * NC;
    const float tr0 = target_x[obase + 0];
    const float tr1 = target_x[obase + 1];
    const float tr2 = target_x[obase + 2];

    // ---- wait for prep's stores (d_q*, d_runi, out-init) ----
    asm volatile("griddepcontrol.wait;" ::: "memory");

    const float4 runi = d_runi;   // broadcast LDG (L2-hot after first block)

    // stage: 48 threads, one LDG.128 each
    if (tid < CHUNK_G)                 s1[tid] = d_q1[gbase + tid];
    else if (tid < CHUNK_G + CHUNK_G / 2)
        ((float4*)s2)[tid - CHUNK_G] = ((const float4*)(d_q2 + gbase))[tid - CHUNK_G];

    __syncthreads();

    float acc0 = 0.f, acc1 = 0.f, acc2 = 0.f;

    if (runi.w != 0.0f) {
        // ======== FAST PATH ========
        const float tp0 = tr0 * runi.x;
        const float tp1 = tr1 * runi.y;
        const float tp2 = tr2 * runi.z;

        #pragma unroll 8
        for (int gi = 0; gi < CHUNK_G; gi++) {
            const float4 q  = s1[gi];   // {2x0, 2x1, 2x2, h0'}
            const float2 hh = s2[gi];   // {h1', h2'}
            acc0 += q.w  * ex2f(q.x * tp0);
            acc1 += hh.x * ex2f(q.y * tp1);
            acc2 += hh.y * ex2f(q.z * tp2);
        }
        // per-target constant factor 2^(-t'^2)
        acc0 *= ex2f(-tp0 * tp0);
        acc1 *= ex2f(-tp1 * tp1);
        acc2 *= ex2f(-tp2 * tp2);
    } else {
        // ======== GENERAL PATH (cold): per-(k,c) scales, direct loads ========
        float a2[NK][NC];
        #pragma unroll
        for (int k = 0; k < NK; k++)
            #pragma unroll
            for (int c = 0; c < NC; c++) {
                float s   = __expf(sigma[k * NC + c]) + 1e-6f;
                float inv = 1.0f / s;
                a2[k][c]  = -0.5f * 1.4426950408889634f * inv * inv;
            }
        float gw[NK];
        #pragma unroll
        for (int k = 0; k < NK; k++) gw[k] = __ldg(&g_w[k]);

        const float* xg = x_grid + gbase * NC;
        const float* hg = h_grid + gbase * NK * NC;
        for (int gi = 0; gi < CHUNK_G; gi++) {
            const float* xp = xg + gi * NC;
            const float x0 = __ldg(&xp[0]), x1 = __ldg(&xp[1]), x2 = __ldg(&xp[2]);
            const float u0 = (x0 - tr0) * (x0 - tr0);
            const float u1 = (x1 - tr1) * (x1 - tr1);
            const float u2 = (x2 - tr2) * (x2 - tr2);
            const float* hp = hg + gi * NK * NC;
            #pragma unroll
            for (int k = 0; k < NK; k++) {
                acc0 += gw[k] * __ldg(&hp[k * NC + 0]) * ex2f(a2[k][0] * u0);
                acc1 += gw[k] * __ldg(&hp[k * NC + 1]) * ex2f(a2[k][1] * u1);
                acc2 += gw[k] * __ldg(&hp[k * NC + 2]) * ex2f(a2[k][2] * u2);
            }
        }
    }

    // fire-and-forget REDs into bias-initialized out
    atomicAdd(&out[obase + 0], acc0);
    atomicAdd(&out[obase + 1], acc1);
    atomicAdd(&out[obase + 2], acc2);
}

extern "C" void kernel_launch(void* const* d_in, const int* in_sizes, int n_in,
                              void* d_out, int out_size)
{
    const float* x_grid   = (const float*)d_in[0];  // (8, 512, 3)
    const float* h_grid   = (const float*)d_in[1];  // (8, 512, 5, 3)
    const float* target_x = (const float*)d_in[2];  // (8, 1024, 3)
    const float* sigma    = (const float*)d_in[3];  // (5, 3)
    const float* g_w      = (const float*)d_in[4];  // (1, 5)
    const float* g_b      = (const float*)d_in[5];  // (1,)
    float* out = (float*)d_out;                     // (8, 1024, 3)

    // prep: 16 fold blocks + 24 out-init blocks
    prep_kernel<<<40, PREP_TPB>>>(x_grid, h_grid, sigma, g_w, g_b, (float4*)out);

    // main with Programmatic Dependent Launch (overlaps prep)
    cudaLaunchConfig_t cfg = {};
    cfg.gridDim  = dim3(TGRP, NCHUNK, NB);   // 8 x 16 x 8 = 1024 blocks
    cfg.blockDim = dim3(MAIN_TPB, 1, 1);
    cudaLaunchAttribute attr[1];
    attr[0].id = cudaLaunchAttributeProgrammaticStreamSerialization;
    attr[0].val.programmaticStreamSerializationAllowed = 1;
    cfg.attrs = attr;
    cfg.numAttrs = 1;
    cudaLaunchKernelEx(&cfg, main_kernel, x_grid, h_grid, target_x, sigma, g_w, out);
}

// round 16
// speedup vs baseline: 1.0322x; 1.0322x over previous
#include <cuda_runtime.h>
#include <math.h>

#define NB 8
#define NG 512
#define NT 1024
#define NK 5
#define NC 3

#define TPB 128
#define TGRP (NT / TPB)          // 8 target-groups
#define NCHUNK 8
#define CHUNK_G (NG / NCHUNK)    // 64 grid rows per chunk

// replay-safe scratch: zero-init statically; finalize resets before exit
__device__ float        d_scratch[NB * NT * NC];
__device__ unsigned int d_count[NB * TGRP];

__device__ __forceinline__ float ex2f(float x) {
    float y;
    asm("ex2.approx.ftz.f32 %0, %1;" : "=f"(y) : "f"(x));
    return y;
}

__global__ __launch_bounds__(TPB)
void fused_kernel(const float* __restrict__ x_grid,
                  const float* __restrict__ h_grid,
                  const float* __restrict__ target_x,
                  const float* __restrict__ sigma,
                  const float* __restrict__ g_w,
                  const float* __restrict__ g_b,
                  float* __restrict__ out)
{
    // raw bounce: h chunk 960 floats (240 f4) + x chunk 192 floats (48 f4)
    __shared__ __align__(16) float  rawbuf[CHUNK_G * NK * NC + CHUNK_G * NC];
    __shared__ __align__(16) float4 s1[CHUNK_G];   // {2x0',2x1',2x2', h0'}
    __shared__ __align__(16) float2 s2[CHUNK_G];   // {h1', h2'}
    __shared__ float s_r[NC];
    __shared__ int   s_uni;
    __shared__ int   s_last;

    const int tid    = threadIdx.x;
    const int warp   = tid >> 5;
    const int lane   = tid & 31;
    const int tgroup = blockIdx.x;
    const int chunk  = blockIdx.y;
    const int b      = blockIdx.z;
    const int g0     = chunk * CHUNK_G;
    const int gbase  = b * NG + g0;

    const float* xg = x_grid + gbase * NC;
    const float* hg = h_grid + gbase * NK * NC;

    // ---- prologue: warp0 coeffs (lane-parallel) || warps 1-3 stage raw ----
    if (warp == 0) {
        float sv = 1.0f;
        if (lane < NK * NC) sv = __expf(sigma[lane]) + 1e-6f;    // lane = k*3+c
        float s0 = __shfl_sync(0xffffffffu, sv, lane % NC);
        bool ok  = (lane < NK * NC) ? (sv == s0) : true;
        unsigned m = __ballot_sync(0xffffffffu, ok);
        if (lane == 0) s_uni = (m == 0xffffffffu);
        if (lane < NC) s_r[lane] = 0.84932180028802f / sv;       // sqrt(0.5*log2e)/s
    } else {
        // 288 float4 loads by 96 threads: 240 h-vectors then 48 x-vectors
        const float4* hg4 = (const float4*)hg;
        const float4* xg4 = (const float4*)xg;
        float4* rb4 = (float4*)rawbuf;
        const int i = tid - 32;
        #pragma unroll
        for (int j = 0; j < 3; j++) {
            const int v = i + j * 96;
            if (v < 240) rb4[v] = hg4[v];
            else         rb4[v] = xg4[v - 240];
        }
    }

    // per-thread target (raw) — overlaps with staging latency
    const int t     = tgroup * TPB + tid;
    const int obase = (b * NT + t) * NC;
    const float tr0 = target_x[obase + 0];
    const float tr1 = target_x[obase + 1];
    const float tr2 = target_x[obase + 2];

    __syncthreads();
    const int uni = s_uni;

    float acc0 = 0.f, acc1 = 0.f, acc2 = 0.f;

    if (uni) {
        // ---- fold: 64 threads, one row each ----
        if (tid < CHUNK_G) {
            const float* hp = rawbuf + tid * (NK * NC);          // stride 15: conflict-free
            float h0 = 0.f, h1 = 0.f, h2 = 0.f;
            #pragma unroll
            for (int k = 0; k < NK; k++) {
                const float w = g_w[k];                           // broadcast, L1-hot
                h0 += w * hp[k * NC + 0];
                h1 += w * hp[k * NC + 1];
                h2 += w * hp[k * NC + 2];
            }
            const float* xp = rawbuf + CHUNK_G * NK * NC + tid * NC;
            const float sx0 = xp[0] * s_r[0];
            const float sx1 = xp[1] * s_r[1];
            const float sx2 = xp[2] * s_r[2];
            h0 *= ex2f(-sx0 * sx0);
            h1 *= ex2f(-sx1 * sx1);
            h2 *= ex2f(-sx2 * sx2);
            s1[tid] = make_float4(2.f * sx0, 2.f * sx1, 2.f * sx2, h0);
            s2[tid] = make_float2(h1, h2);
        }
        const float tp0 = tr0 * s_r[0];
        const float tp1 = tr1 * s_r[1];
        const float tp2 = tr2 * s_r[2];
        __syncthreads();

        // ---- 64-iter loop: LDS.128 + LDS.64 + 3x(FMUL,EX2,FFMA) ----
        #pragma unroll 8
        for (int gi = 0; gi < CHUNK_G; gi++) {
            const float4 q  = s1[gi];
            const float2 hh = s2[gi];
            acc0 += q.w  * ex2f(q.x * tp0);
            acc1 += hh.x * ex2f(q.y * tp1);
            acc2 += hh.y * ex2f(q.z * tp2);
        }
        acc0 *= ex2f(-tp0 * tp0);
        acc1 *= ex2f(-tp1 * tp1);
        acc2 *= ex2f(-tp2 * tp2);
    } else {
        // ---- GENERAL PATH (cold): per-(k,c) scales, direct loads ----
        float a2[NK][NC];
        #pragma unroll
        for (int k = 0; k < NK; k++)
            #pragma unroll
            for (int c = 0; c < NC; c++) {
                float s   = __expf(sigma[k * NC + c]) + 1e-6f;
                float inv = 1.0f / s;
                a2[k][c]  = -0.5f * 1.4426950408889634f * inv * inv;
            }
        float gw[NK];
        #pragma unroll
        for (int k = 0; k < NK; k++) gw[k] = __ldg(&g_w[k]);

        for (int gi = 0; gi < CHUNK_G; gi++) {
            const float* xp = xg + gi * NC;
            const float x0 = __ldg(&xp[0]), x1 = __ldg(&xp[1]), x2 = __ldg(&xp[2]);
            const float u0 = (x0 - tr0) * (x0 - tr0);
            const float u1 = (x1 - tr1) * (x1 - tr1);
            const float u2 = (x2 - tr2) * (x2 - tr2);
            const float* hp = hg + gi * NK * NC;
            #pragma unroll
            for (int k = 0; k < NK; k++) {
                acc0 += gw[k] * __ldg(&hp[k * NC + 0]) * ex2f(a2[k][0] * u0);
                acc1 += gw[k] * __ldg(&hp[k * NC + 1]) * ex2f(a2[k][1] * u1);
                acc2 += gw[k] * __ldg(&hp[k * NC + 2]) * ex2f(a2[k][2] * u2);
            }
        }
    }

    // ---- partials into zero-init scratch (fire-and-forget RED) ----
    atomicAdd(&d_scratch[obase + 0], acc0);
    atomicAdd(&d_scratch[obase + 1], acc1);
    atomicAdd(&d_scratch[obase + 2], acc2);

    __threadfence();            // release: this thread's REDs globally visible
    __syncthreads();
    if (tid == 0) {
        unsigned int v = atomicAdd(&d_count[b * TGRP + tgroup], 1u);
        s_last = (v == NCHUNK - 1) ? 1 : 0;
    }
    __syncthreads();

    if (s_last) {
        __threadfence();        // acquire side
        const float bb = g_b[0];
        float s0 = __ldcg(&d_scratch[obase + 0]);
        float s1v = __ldcg(&d_scratch[obase + 1]);
        float s2v = __ldcg(&d_scratch[obase + 2]);
        out[obase + 0] = s0 + bb;
        out[obase + 1] = s1v + bb;
        out[obase + 2] = s2v + bb;
        // reset for next graph replay
        d_scratch[obase + 0] = 0.0f;
        d_scratch[obase + 1] = 0.0f;
        d_scratch[obase + 2] = 0.0f;
        if (tid == 0) d_count[b * TGRP + tgroup] = 0u;
    }
}

extern "C" void kernel_launch(void* const* d_in, const int* in_sizes, int n_in,
                              void* d_out, int out_size)
{
    const float* x_grid   = (const float*)d_in[0];  // (8, 512, 3)
    const float* h_grid   = (const float*)d_in[1];  // (8, 512, 5, 3)
    const float* target_x = (const float*)d_in[2];  // (8, 1024, 3)
    const float* sigma    = (const float*)d_in[3];  // (5, 3)
    const float* g_w      = (const float*)d_in[4];  // (1, 5)
    const float* g_b      = (const float*)d_in[5];  // (1,)
    float* out = (float*)d_out;                     // (8, 1024, 3)

    dim3 grid(TGRP, NCHUNK, NB);   // 8 x 8 x 8 = 512 blocks of 128
    fused_kernel<<<grid, TPB>>>(x_grid, h_grid, target_x, sigma, g_w, g_b, out);
}

// round 17
// speedup vs baseline: 1.0969x; 1.0627x over previous
#include <cuda_runtime.h>
#include <math.h>

#define NB 8
#define NG 512
#define NT 1024
#define NK 5
#define NC 3

#define TPB 128
#define TGRP (NT / TPB)          // 8 target-groups
#define NCHUNK 16
#define CHUNK_G (NG / NCHUNK)    // 32 grid rows per chunk

// replay-safe scratch: zero-init statically; finalize resets before exit
__device__ float        d_scratch[NB * NT * NC];
__device__ unsigned int d_count[NB * TGRP];

__device__ __forceinline__ float ex2f(float x) {
    float y;
    asm("ex2.approx.ftz.f32 %0, %1;" : "=f"(y) : "f"(x));
    return y;
}

__global__ __launch_bounds__(TPB)
void fused_kernel(const float* __restrict__ x_grid,
                  const float* __restrict__ h_grid,
                  const float* __restrict__ target_x,
                  const float* __restrict__ sigma,
                  const float* __restrict__ g_w,
                  const float* __restrict__ g_b,
                  float* __restrict__ out)
{
    // raw bounce: h chunk 480 floats (120 f4) + x chunk 96 floats (24 f4)
    __shared__ __align__(16) float  rawbuf[CHUNK_G * NK * NC + CHUNK_G * NC];
    __shared__ __align__(16) float4 s1[CHUNK_G];   // {2x0',2x1',2x2', h0'}
    __shared__ __align__(16) float2 s2[CHUNK_G];   // {h1', h2'}
    __shared__ float s_r[NC];
    __shared__ int   s_uni;
    __shared__ int   s_last;

    const int tid    = threadIdx.x;
    const int warp   = tid >> 5;
    const int lane   = tid & 31;
    const int tgroup = blockIdx.x;
    const int chunk  = blockIdx.y;
    const int b      = blockIdx.z;
    const int g0     = chunk * CHUNK_G;
    const int gbase  = b * NG + g0;

    const float* xg = x_grid + gbase * NC;
    const float* hg = h_grid + gbase * NK * NC;

    // ---- prologue: warp0 coeffs (lane-parallel) || warps 1-3 stage raw ----
    if (warp == 0) {
        float sv = 1.0f;
        if (lane < NK * NC) sv = __expf(sigma[lane]) + 1e-6f;    // lane = k*3+c
        float s0 = __shfl_sync(0xffffffffu, sv, lane % NC);
        bool ok  = (lane < NK * NC) ? (sv == s0) : true;
        unsigned m = __ballot_sync(0xffffffffu, ok);
        if (lane == 0) s_uni = (m == 0xffffffffu);
        if (lane < NC) s_r[lane] = 0.84932180028802f / sv;       // sqrt(0.5*log2e)/s
    } else {
        // 144 float4 loads by 96 threads: 120 h-vectors then 24 x-vectors
        const float4* hg4 = (const float4*)hg;
        const float4* xg4 = (const float4*)xg;
        float4* rb4 = (float4*)rawbuf;
        const int i = tid - 32;
        #pragma unroll
        for (int j = 0; j < 2; j++) {
            const int v = i + j * 96;
            if (v < 120)      rb4[v] = hg4[v];
            else if (v < 144) rb4[v] = xg4[v - 120];
        }
    }

    // per-thread target (raw) — overlaps with staging latency
    const int t     = tgroup * TPB + tid;
    const int obase = (b * NT + t) * NC;
    const float tr0 = target_x[obase + 0];
    const float tr1 = target_x[obase + 1];
    const float tr2 = target_x[obase + 2];

    __syncthreads();
    const int uni = s_uni;

    float acc0 = 0.f, acc1 = 0.f, acc2 = 0.f;

    if (uni) {
        // ---- fold: 32 threads, one row each (stride-15 LDS: conflict-free) ----
        if (tid < CHUNK_G) {
            const float* hp = rawbuf + tid * (NK * NC);
            float h0 = 0.f, h1 = 0.f, h2 = 0.f;
            #pragma unroll
            for (int k = 0; k < NK; k++) {
                const float w = __ldg(&g_w[k]);                   // broadcast, L1-hot
                h0 += w * hp[k * NC + 0];
                h1 += w * hp[k * NC + 1];
                h2 += w * hp[k * NC + 2];
            }
            const float* xp = rawbuf + CHUNK_G * NK * NC + tid * NC;
            const float sx0 = xp[0] * s_r[0];
            const float sx1 = xp[1] * s_r[1];
            const float sx2 = xp[2] * s_r[2];
            h0 *= ex2f(-sx0 * sx0);
            h1 *= ex2f(-sx1 * sx1);
            h2 *= ex2f(-sx2 * sx2);
            s1[tid] = make_float4(2.f * sx0, 2.f * sx1, 2.f * sx2, h0);
            s2[tid] = make_float2(h1, h2);
        }
        const float tp0 = tr0 * s_r[0];
        const float tp1 = tr1 * s_r[1];
        const float tp2 = tr2 * s_r[2];
        __syncthreads();

        // ---- 32-iter loop: LDS.128 + LDS.64 + 3x(FMUL,EX2,FFMA) ----
        #pragma unroll 8
        for (int gi = 0; gi < CHUNK_G; gi++) {
            const float4 q  = s1[gi];
            const float2 hh = s2[gi];
            acc0 += q.w  * ex2f(q.x * tp0);
            acc1 += hh.x * ex2f(q.y * tp1);
            acc2 += hh.y * ex2f(q.z * tp2);
        }
        acc0 *= ex2f(-tp0 * tp0);
        acc1 *= ex2f(-tp1 * tp1);
        acc2 *= ex2f(-tp2 * tp2);
    } else {
        // ---- GENERAL PATH (cold): per-(k,c) scales, direct loads ----
        float a2[NK][NC];
        #pragma unroll
        for (int k = 0; k < NK; k++)
            #pragma unroll
            for (int c = 0; c < NC; c++) {
                float s   = __expf(sigma[k * NC + c]) + 1e-6f;
                float inv = 1.0f / s;
                a2[k][c]  = -0.5f * 1.4426950408889634f * inv * inv;
            }
        float gw[NK];
        #pragma unroll
        for (int k = 0; k < NK; k++) gw[k] = __ldg(&g_w[k]);

        for (int gi = 0; gi < CHUNK_G; gi++) {
            const float* xp = xg + gi * NC;
            const float x0 = __ldg(&xp[0]), x1 = __ldg(&xp[1]), x2 = __ldg(&xp[2]);
            const float u0 = (x0 - tr0) * (x0 - tr0);
            const float u1 = (x1 - tr1) * (x1 - tr1);
            const float u2 = (x2 - tr2) * (x2 - tr2);
            const float* hp = hg + gi * NK * NC;
            #pragma unroll
            for (int k = 0; k < NK; k++) {
                acc0 += gw[k] * __ldg(&hp[k * NC + 0]) * ex2f(a2[k][0] * u0);
                acc1 += gw[k] * __ldg(&hp[k * NC + 1]) * ex2f(a2[k][1] * u1);
                acc2 += gw[k] * __ldg(&hp[k * NC + 2]) * ex2f(a2[k][2] * u2);
            }
        }
    }

    // ---- partials into zero-init scratch (fire-and-forget RED) ----
    atomicAdd(&d_scratch[obase + 0], acc0);
    atomicAdd(&d_scratch[obase + 1], acc1);
    atomicAdd(&d_scratch[obase + 2], acc2);

    __threadfence();            // release: this thread's REDs globally visible
    __syncthreads();
    if (tid == 0) {
        unsigned int v = atomicAdd(&d_count[b * TGRP + tgroup], 1u);
        s_last = (v == NCHUNK - 1) ? 1 : 0;
    }
    __syncthreads();

    if (s_last) {
        __threadfence();        // acquire side
        const float bb = g_b[0];
        float s0  = __ldcg(&d_scratch[obase + 0]);
        float s1v = __ldcg(&d_scratch[obase + 1]);
        float s2v = __ldcg(&d_scratch[obase + 2]);
        out[obase + 0] = s0  + bb;
        out[obase + 1] = s1v + bb;
        out[obase + 2] = s2v + bb;
        // reset for next graph replay
        d_scratch[obase + 0] = 0.0f;
        d_scratch[obase + 1] = 0.0f;
        d_scratch[obase + 2] = 0.0f;
        if (tid == 0) d_count[b * TGRP + tgroup] = 0u;
    }
}

extern "C" void kernel_launch(void* const* d_in, const int* in_sizes, int n_in,
                              void* d_out, int out_size)
{
    const float* x_grid   = (const float*)d_in[0];  // (8, 512, 3)
    const float* h_grid   = (const float*)d_in[1];  // (8, 512, 5, 3)
    const float* target_x = (const float*)d_in[2];  // (8, 1024, 3)
    const float* sigma    = (const float*)d_in[3];  // (5, 3)
    const float* g_w      = (const float*)d_in[4];  // (1, 5)
    const float* g_b      = (const float*)d_in[5];  // (1,)
    float* out = (float*)d_out;                     // (8, 1024, 3)

    dim3 grid(TGRP, NCHUNK, NB);   // 8 x 16 x 8 = 1024 blocks of 128
    fused_kernel<<<grid, TPB>>>(x_grid, h_grid, target_x, sigma, g_w, g_b, out);
}